// round 11
// baseline (speedup 1.0000x reference)
#include <cuda_runtime.h>
#include <cstdint>

#define MAXN 100000
#define MAXE 3200000
#define DDIM 512
#define CDIM 40

// ---- scratch (static device globals; no runtime alloc) ----
__device__ int   g_cnt[MAXN];
__device__ int   g_rowptr[MAXN + 1];
__device__ int   g_cursor[MAXN];
__device__ int   g_col[MAXE];
__device__ float g_wgt[MAXE];          // dinv[src] per bucketed edge
__device__ float g_dinv[MAXN];
__device__ float g_y0[MAXN * CDIM];
__device__ float g_y1[MAXN * CDIM];

// ---------------- zero counts ----------------
__global__ void k_zero(int N) {
    int i = blockIdx.x * blockDim.x + threadIdx.x;
    if (i < N) g_cnt[i] = 0;
}

// ---------------- in-degree histogram (edge_index is int32!) ----------------
__global__ void k_hist(const int* __restrict__ ei, int E) {
    int e = blockIdx.x * blockDim.x + threadIdx.x;
    if (e < E) {
        int d = ei[E + e];   // dst row
        atomicAdd(&g_cnt[d], 1);
    }
}

// ---------------- single-block exclusive scan + dinv ----------------
__global__ void k_scan(int N) {
    __shared__ int warpsum[32];
    __shared__ int s_carry;
    int tid = threadIdx.x;            // 1024
    int lane = tid & 31, wid = tid >> 5;
    if (tid == 0) s_carry = 0;
    __syncthreads();
    for (int base = 0; base < N; base += 1024) {
        int i = base + tid;
        int v = (i < N) ? g_cnt[i] : 0;
        int x = v;
#pragma unroll
        for (int off = 1; off < 32; off <<= 1) {
            int t = __shfl_up_sync(0xffffffffu, x, off);
            if (lane >= off) x += t;
        }
        if (lane == 31) warpsum[wid] = x;
        __syncthreads();
        if (wid == 0) {
            int w = warpsum[lane];
#pragma unroll
            for (int off = 1; off < 32; off <<= 1) {
                int t = __shfl_up_sync(0xffffffffu, w, off);
                if (lane >= off) w += t;
            }
            warpsum[lane] = w;
        }
        __syncthreads();
        int incl = x + ((wid > 0) ? warpsum[wid - 1] : 0);
        int carry = s_carry;
        if (i < N) {
            int excl = carry + incl - v;
            g_rowptr[i] = excl;
            g_cursor[i] = excl;
            g_dinv[i]   = rsqrtf((float)(v + 1));  // +1 self loop
        }
        __syncthreads();
        if (tid == 1023) s_carry = carry + incl;
        __syncthreads();
    }
    if (threadIdx.x == 0) g_rowptr[N] = s_carry;
}

// ---------------- bucket edges by dst (also store dinv[src]) ----------------
__global__ void k_scatter(const int* __restrict__ ei, int E) {
    int e = blockIdx.x * blockDim.x + threadIdx.x;
    if (e < E) {
        int s = ei[e];
        int d = ei[E + e];
        int pos = atomicAdd(&g_cursor[d], 1);
        g_col[pos] = s;
        g_wgt[pos] = g_dinv[s];
    }
}

// ---------------- tiled GEMM: g_y0 = x @ W^T ----------------
// block: 128 threads, tile 64 rows x 40 cols, K-chunk 64
// thread tile: 4 rows (stride 16) x 5 cols
__global__ void k_gemm(const float* __restrict__ x, const float* __restrict__ W, int N) {
    __shared__ float xs[64 * 68];
    __shared__ float ws[40 * 68];
    int tid = threadIdx.x;
    int rg = tid & 15;       // 0..15
    int cg = tid >> 4;       // 0..7
    int row0 = blockIdx.x * 64;

    float acc[4][5];
#pragma unroll
    for (int i = 0; i < 4; i++)
#pragma unroll
        for (int j = 0; j < 5; j++) acc[i][j] = 0.f;

    for (int kc = 0; kc < DDIM; kc += 64) {
        // load x tile: 64 rows x 64 floats = 1024 float4, 8 per thread
#pragma unroll
        for (int t = 0; t < 8; t++) {
            int idx = tid + t * 128;
            int r = idx >> 4, q = idx & 15;
            float4 v = make_float4(0.f, 0.f, 0.f, 0.f);
            int gr = row0 + r;
            if (gr < N)
                v = *reinterpret_cast<const float4*>(x + (size_t)gr * DDIM + kc + 4 * q);
            *reinterpret_cast<float4*>(&xs[r * 68 + 4 * q]) = v;
        }
        // load w tile: 40 x 64 floats = 640 float4, 5 per thread
#pragma unroll
        for (int t = 0; t < 5; t++) {
            int idx = tid + t * 128;
            int c = idx >> 4, q = idx & 15;
            float4 v = *reinterpret_cast<const float4*>(W + (size_t)c * DDIM + kc + 4 * q);
            *reinterpret_cast<float4*>(&ws[c * 68 + 4 * q]) = v;
        }
        __syncthreads();
#pragma unroll
        for (int q = 0; q < 16; q++) {
            float4 xv[4], wv[5];
#pragma unroll
            for (int i = 0; i < 4; i++)
                xv[i] = *reinterpret_cast<const float4*>(&xs[(rg + 16 * i) * 68 + 4 * q]);
#pragma unroll
            for (int j = 0; j < 5; j++)
                wv[j] = *reinterpret_cast<const float4*>(&ws[(cg * 5 + j) * 68 + 4 * q]);
#pragma unroll
            for (int i = 0; i < 4; i++)
#pragma unroll
                for (int j = 0; j < 5; j++) {
                    acc[i][j] += xv[i].x * wv[j].x;
                    acc[i][j] += xv[i].y * wv[j].y;
                    acc[i][j] += xv[i].z * wv[j].z;
                    acc[i][j] += xv[i].w * wv[j].w;
                }
        }
        __syncthreads();
    }
#pragma unroll
    for (int i = 0; i < 4; i++) {
        int gr = row0 + rg + 16 * i;
        if (gr < N) {
#pragma unroll
            for (int j = 0; j < 5; j++)
                g_y0[(size_t)gr * CDIM + cg * 5 + j] = acc[i][j];
        }
    }
}

// ---------------- propagation hop (warp per dst node) ----------------
// hop==0: y1 <- S y0 ; hop==1: out <- log_softmax(S y1 + b)
// Edge loop unrolled 4-wide: 8 independent y-row gathers in flight (MLP>=4).
__global__ void k_prop(const float* __restrict__ bias, float* __restrict__ out,
                       int N, int hop) {
    int g = (blockIdx.x * blockDim.x + threadIdx.x) >> 5;
    int lane = threadIdx.x & 31;
    if (g >= N) return;
    const float* __restrict__ yin = (hop == 0) ? g_y0 : g_y1;
    float* __restrict__ yout = g_y1;
    bool hi = (lane < CDIM - 32);

    float di = __ldg(&g_dinv[g]);
    const float* yr0 = yin + (size_t)g * CDIM;
    float a1 = di * di * __ldg(&yr0[lane]);
    float a2 = hi ? di * di * __ldg(&yr0[32 + lane]) : 0.f;

    int beg = g_rowptr[g], end = g_rowptr[g + 1];
    int i = beg;
    for (; i + 3 < end; i += 4) {
        int   s0 = __ldg(&g_col[i]);
        int   s1 = __ldg(&g_col[i + 1]);
        int   s2 = __ldg(&g_col[i + 2]);
        int   s3 = __ldg(&g_col[i + 3]);
        float w0 = di * __ldg(&g_wgt[i]);
        float w1 = di * __ldg(&g_wgt[i + 1]);
        float w2 = di * __ldg(&g_wgt[i + 2]);
        float w3 = di * __ldg(&g_wgt[i + 3]);
        const float* p0 = yin + (size_t)s0 * CDIM;
        const float* p1 = yin + (size_t)s1 * CDIM;
        const float* p2 = yin + (size_t)s2 * CDIM;
        const float* p3 = yin + (size_t)s3 * CDIM;
        float v0a = __ldg(&p0[lane]);
        float v1a = __ldg(&p1[lane]);
        float v2a = __ldg(&p2[lane]);
        float v3a = __ldg(&p3[lane]);
        float v0b = hi ? __ldg(&p0[32 + lane]) : 0.f;
        float v1b = hi ? __ldg(&p1[32 + lane]) : 0.f;
        float v2b = hi ? __ldg(&p2[32 + lane]) : 0.f;
        float v3b = hi ? __ldg(&p3[32 + lane]) : 0.f;
        a1 += w0 * v0a; a1 += w1 * v1a; a1 += w2 * v2a; a1 += w3 * v3a;
        a2 += w0 * v0b; a2 += w1 * v1b; a2 += w2 * v2b; a2 += w3 * v3b;
    }
    for (; i < end; i++) {
        int   s0 = __ldg(&g_col[i]);
        float w0 = di * __ldg(&g_wgt[i]);
        const float* p0 = yin + (size_t)s0 * CDIM;
        a1 += w0 * __ldg(&p0[lane]);
        if (hi) a2 += w0 * __ldg(&p0[32 + lane]);
    }

    if (hop == 0) {
        yout[(size_t)g * CDIM + lane] = a1;
        if (hi) yout[(size_t)g * CDIM + 32 + lane] = a2;
    } else {
        a1 += bias[lane];
        if (hi) a2 += bias[32 + lane];
        float m = a1;
        if (hi) m = fmaxf(m, a2);
#pragma unroll
        for (int off = 16; off; off >>= 1)
            m = fmaxf(m, __shfl_xor_sync(0xffffffffu, m, off));
        float se = expf(a1 - m) + (hi ? expf(a2 - m) : 0.f);
#pragma unroll
        for (int off = 16; off; off >>= 1)
            se += __shfl_xor_sync(0xffffffffu, se, off);
        float l = m + logf(se);
        out[(size_t)g * CDIM + lane] = a1 - l;
        if (hi) out[(size_t)g * CDIM + 32 + lane] = a2 - l;
    }
}

extern "C" void kernel_launch(void* const* d_in, const int* in_sizes, int n_in,
                              void* d_out, int out_size) {
    const float* x  = (const float*)d_in[0];
    const int*   ei = (const int*)d_in[1];   // int32! (JAX x64 disabled)
    const float* W  = (const float*)d_in[2];
    const float* b  = (const float*)d_in[3];
    float* out = (float*)d_out;

    int N = in_sizes[0] / DDIM;
    int E = in_sizes[1] / 2;
    if (N > MAXN) N = MAXN;
    if (E > MAXE) E = MAXE;

    // 1) degree histogram
    k_zero<<<(N + 1023) / 1024, 1024>>>(N);
    k_hist<<<(E + 255) / 256, 256>>>(ei, E);
    // 2) rowptr + cursor + dinv
    k_scan<<<1, 1024>>>(N);
    // 3) bucket edges by dst (+ precompute dinv[src])
    k_scatter<<<(E + 255) / 256, 256>>>(ei, E);
    // 4) project first: y0 = x @ W^T  (commutes with propagation)
    k_gemm<<<(N + 63) / 64, 128>>>(x, W, N);
    // 5) hop 1: y1 = S y0
    int pb = (N * 32 + 255) / 256;
    k_prop<<<pb, 256>>>(b, out, N, 0);
    // 6) hop 2 fused with bias + log_softmax
    k_prop<<<pb, 256>>>(b, out, N, 1);
}

// round 13
// speedup vs baseline: 1.2535x; 1.2535x over previous
#include <cuda_runtime.h>
#include <cstdint>

#define MAXN 100000
#define MAXE 3200000
#define DDIM 512
#define CDIM 40
#define SCAN_B 1024          // elements per scan block
#define MAXB ((MAXN + SCAN_B - 1) / SCAN_B)

// ---- scratch (static device globals; no runtime alloc) ----
__device__ int   g_cnt[MAXN];
__device__ int   g_rowptr[MAXN + 1];
__device__ int   g_cursor[MAXN];
__device__ int2  g_cw[MAXE];           // packed {src, bitcast(dinv[src])}
__device__ float g_dinv[MAXN];
__device__ int   g_bsum[MAXB];
__device__ int   g_boff[MAXB];
__device__ float g_y0[MAXN * CDIM];
__device__ float g_y1[MAXN * CDIM];

// packed fp32x2 FMA: d.lo += a.lo*b.lo ; d.hi += a.hi*b.hi  (1 instr, 2 FMAs)
__device__ __forceinline__ void ffma2(unsigned long long& d,
                                      unsigned long long a,
                                      unsigned long long b) {
    asm("fma.rn.f32x2 %0, %1, %2, %0;" : "+l"(d) : "l"(a), "l"(b));
}

// ---------------- zero counts ----------------
__global__ void k_zero(int N) {
    int i = blockIdx.x * blockDim.x + threadIdx.x;
    if (i < N) g_cnt[i] = 0;
}

// ---------------- in-degree histogram (edge_index is int32) ----------------
__global__ void k_hist(const int* __restrict__ ei, int E) {
    int e = blockIdx.x * blockDim.x + threadIdx.x;
    if (e < E) atomicAdd(&g_cnt[ei[E + e]], 1);
}

// ---------------- decoupled scan, phase 1: per-block reduce ----------------
__global__ void k_reduce(int N) {
    __shared__ int wsum[32];
    int t = threadIdx.x;                     // 1024
    int i = blockIdx.x * SCAN_B + t;
    int v = (i < N) ? g_cnt[i] : 0;
    int lane = t & 31, wid = t >> 5;
#pragma unroll
    for (int off = 16; off; off >>= 1) v += __shfl_xor_sync(0xffffffffu, v, off);
    if (lane == 0) wsum[wid] = v;
    __syncthreads();
    if (wid == 0) {
        int s = (lane < 32) ? wsum[lane] : 0;
#pragma unroll
        for (int off = 16; off; off >>= 1) s += __shfl_xor_sync(0xffffffffu, s, off);
        if (lane == 0) g_bsum[blockIdx.x] = s;
    }
}

// ---------------- phase 2: scan the (<=128) block sums ----------------
__global__ void k_scansums(int nb, int N) {
    __shared__ int wsum[4];
    int t = threadIdx.x;                     // 128
    int lane = t & 31, wid = t >> 5;
    int v = (t < nb) ? g_bsum[t] : 0;
    int x = v;
#pragma unroll
    for (int off = 1; off < 32; off <<= 1) {
        int u = __shfl_up_sync(0xffffffffu, x, off);
        if (lane >= off) x += u;
    }
    if (lane == 31) wsum[wid] = x;
    __syncthreads();
    int add = 0;
    for (int w = 0; w < wid; w++) add += wsum[w];
    int incl = x + add;
    if (t < nb) g_boff[t] = incl - v;        // exclusive
    if (t == 127) g_rowptr[N] = incl;        // grand total
}

// ---------------- phase 3: per-block scan + rowptr/cursor/dinv ----------------
__global__ void k_scanfinal(int N) {
    __shared__ int wsum[32];
    int t = threadIdx.x;                     // 1024
    int i = blockIdx.x * SCAN_B + t;
    int lane = t & 31, wid = t >> 5;
    int v = (i < N) ? g_cnt[i] : 0;
    int x = v;
#pragma unroll
    for (int off = 1; off < 32; off <<= 1) {
        int u = __shfl_up_sync(0xffffffffu, x, off);
        if (lane >= off) x += u;
    }
    if (lane == 31) wsum[wid] = x;
    __syncthreads();
    if (wid == 0) {
        int s = wsum[lane];
#pragma unroll
        for (int off = 1; off < 32; off <<= 1) {
            int u = __shfl_up_sync(0xffffffffu, s, off);
            if (lane >= off) s += u;
        }
        wsum[lane] = s;
    }
    __syncthreads();
    int incl = x + ((wid > 0) ? wsum[wid - 1] : 0);
    if (i < N) {
        int excl = g_boff[blockIdx.x] + incl - v;
        g_rowptr[i] = excl;
        g_cursor[i] = excl;
        g_dinv[i]   = rsqrtf((float)(v + 1));  // +1 self loop
    }
}

// ---------------- bucket edges by dst: single packed 8B store ----------------
__global__ void k_scatter(const int* __restrict__ ei, int E) {
    int e = blockIdx.x * blockDim.x + threadIdx.x;
    if (e < E) {
        int s = ei[e];
        int d = ei[E + e];
        int pos = atomicAdd(&g_cursor[d], 1);
        g_cw[pos] = make_int2(s, __float_as_int(g_dinv[s]));
    }
}

// ---------------- tiled GEMM: g_y0 = x @ W^T (fp32x2 packed FMA) ----------
// block: 128 threads, tile 64 rows x 40 cols, K-chunk 64
__global__ void k_gemm(const float* __restrict__ x, const float* __restrict__ W, int N) {
    __shared__ float xs[64 * 68];
    __shared__ float ws[40 * 68];
    int tid = threadIdx.x;
    int rg = tid & 15;       // 0..15
    int cg = tid >> 4;       // 0..7
    int row0 = blockIdx.x * 64;

    unsigned long long acc[4][5];
#pragma unroll
    for (int i = 0; i < 4; i++)
#pragma unroll
        for (int j = 0; j < 5; j++) acc[i][j] = 0ull;

    for (int kc = 0; kc < DDIM; kc += 64) {
#pragma unroll
        for (int t = 0; t < 8; t++) {
            int idx = tid + t * 128;
            int r = idx >> 4, q = idx & 15;
            float4 v = make_float4(0.f, 0.f, 0.f, 0.f);
            int gr = row0 + r;
            if (gr < N)
                v = *reinterpret_cast<const float4*>(x + (size_t)gr * DDIM + kc + 4 * q);
            *reinterpret_cast<float4*>(&xs[r * 68 + 4 * q]) = v;
        }
#pragma unroll
        for (int t = 0; t < 5; t++) {
            int idx = tid + t * 128;
            int c = idx >> 4, q = idx & 15;
            float4 v = *reinterpret_cast<const float4*>(W + (size_t)c * DDIM + kc + 4 * q);
            *reinterpret_cast<float4*>(&ws[c * 68 + 4 * q]) = v;
        }
        __syncthreads();
#pragma unroll
        for (int q = 0; q < 16; q++) {
            ulonglong2 xv[4], wv[5];
#pragma unroll
            for (int i = 0; i < 4; i++)
                xv[i] = *reinterpret_cast<const ulonglong2*>(&xs[(rg + 16 * i) * 68 + 4 * q]);
#pragma unroll
            for (int j = 0; j < 5; j++)
                wv[j] = *reinterpret_cast<const ulonglong2*>(&ws[(cg * 5 + j) * 68 + 4 * q]);
#pragma unroll
            for (int i = 0; i < 4; i++)
#pragma unroll
                for (int j = 0; j < 5; j++) {
                    ffma2(acc[i][j], xv[i].x, wv[j].x);
                    ffma2(acc[i][j], xv[i].y, wv[j].y);
                }
        }
        __syncthreads();
    }
#pragma unroll
    for (int i = 0; i < 4; i++) {
        int gr = row0 + rg + 16 * i;
        if (gr < N) {
#pragma unroll
            for (int j = 0; j < 5; j++) {
                unsigned long long p = acc[i][j];
                float lo = __uint_as_float((unsigned)(p & 0xffffffffu));
                float hi = __uint_as_float((unsigned)(p >> 32));
                g_y0[(size_t)gr * CDIM + cg * 5 + j] = lo + hi;
            }
        }
    }
}

// ---------------- propagation hop (warp per dst node) ----------------
// hop==0: y1 <- S y0 ; hop==1: out <- log_softmax(S y1 + b)
__global__ void k_prop(const float* __restrict__ bias, float* __restrict__ out,
                       int N, int hop) {
    int g = (blockIdx.x * blockDim.x + threadIdx.x) >> 5;
    int lane = threadIdx.x & 31;
    if (g >= N) return;
    const float* __restrict__ yin = (hop == 0) ? g_y0 : g_y1;
    float* __restrict__ yout = g_y1;
    bool hi = (lane < CDIM - 32);

    float di = __ldg(&g_dinv[g]);
    const float* yr0 = yin + (size_t)g * CDIM;
    float a1 = di * di * __ldg(&yr0[lane]);
    float a2 = hi ? di * di * __ldg(&yr0[32 + lane]) : 0.f;

    int beg = g_rowptr[g], end = g_rowptr[g + 1];
    int i = beg;
    for (; i + 3 < end; i += 4) {
        int2 c0 = __ldg(&g_cw[i]);
        int2 c1 = __ldg(&g_cw[i + 1]);
        int2 c2 = __ldg(&g_cw[i + 2]);
        int2 c3 = __ldg(&g_cw[i + 3]);
        float w0 = di * __int_as_float(c0.y);
        float w1 = di * __int_as_float(c1.y);
        float w2 = di * __int_as_float(c2.y);
        float w3 = di * __int_as_float(c3.y);
        const float* p0 = yin + (size_t)c0.x * CDIM;
        const float* p1 = yin + (size_t)c1.x * CDIM;
        const float* p2 = yin + (size_t)c2.x * CDIM;
        const float* p3 = yin + (size_t)c3.x * CDIM;
        float v0a = __ldg(&p0[lane]);
        float v1a = __ldg(&p1[lane]);
        float v2a = __ldg(&p2[lane]);
        float v3a = __ldg(&p3[lane]);
        float v0b = hi ? __ldg(&p0[32 + lane]) : 0.f;
        float v1b = hi ? __ldg(&p1[32 + lane]) : 0.f;
        float v2b = hi ? __ldg(&p2[32 + lane]) : 0.f;
        float v3b = hi ? __ldg(&p3[32 + lane]) : 0.f;
        a1 += w0 * v0a; a1 += w1 * v1a; a1 += w2 * v2a; a1 += w3 * v3a;
        a2 += w0 * v0b; a2 += w1 * v1b; a2 += w2 * v2b; a2 += w3 * v3b;
    }
    for (; i < end; i++) {
        int2 c0 = __ldg(&g_cw[i]);
        float w0 = di * __int_as_float(c0.y);
        const float* p0 = yin + (size_t)c0.x * CDIM;
        a1 += w0 * __ldg(&p0[lane]);
        if (hi) a2 += w0 * __ldg(&p0[32 + lane]);
    }

    if (hop == 0) {
        yout[(size_t)g * CDIM + lane] = a1;
        if (hi) yout[(size_t)g * CDIM + 32 + lane] = a2;
    } else {
        a1 += bias[lane];
        if (hi) a2 += bias[32 + lane];
        float m = a1;
        if (hi) m = fmaxf(m, a2);
#pragma unroll
        for (int off = 16; off; off >>= 1)
            m = fmaxf(m, __shfl_xor_sync(0xffffffffu, m, off));
        float se = expf(a1 - m) + (hi ? expf(a2 - m) : 0.f);
#pragma unroll
        for (int off = 16; off; off >>= 1)
            se += __shfl_xor_sync(0xffffffffu, se, off);
        float l = m + logf(se);
        out[(size_t)g * CDIM + lane] = a1 - l;
        if (hi) out[(size_t)g * CDIM + 32 + lane] = a2 - l;
    }
}

extern "C" void kernel_launch(void* const* d_in, const int* in_sizes, int n_in,
                              void* d_out, int out_size) {
    const float* x  = (const float*)d_in[0];
    const int*   ei = (const int*)d_in[1];   // int32 (JAX x64 disabled)
    const float* W  = (const float*)d_in[2];
    const float* b  = (const float*)d_in[3];
    float* out = (float*)d_out;

    int N = in_sizes[0] / DDIM;
    int E = in_sizes[1] / 2;
    if (N > MAXN) N = MAXN;
    if (E > MAXE) E = MAXE;
    int nb = (N + SCAN_B - 1) / SCAN_B;

    // 1) degree histogram
    k_zero<<<(N + 1023) / 1024, 1024>>>(N);
    k_hist<<<(E + 255) / 256, 256>>>(ei, E);
    // 2) parallel scan -> rowptr + cursor + dinv
    k_reduce<<<nb, 1024>>>(N);
    k_scansums<<<1, 128>>>(nb, N);
    k_scanfinal<<<nb, 1024>>>(N);
    // 3) bucket edges by dst (packed 8B {src, dinv[src]})
    k_scatter<<<(E + 255) / 256, 256>>>(ei, E);
    // 4) project first: y0 = x @ W^T  (commutes with propagation)
    k_gemm<<<(N + 63) / 64, 128>>>(x, W, N);
    // 5) hop 1: y1 = S y0
    int pb = (N * 32 + 255) / 256;
    k_prop<<<pb, 256>>>(b, out, N, 0);
    // 6) hop 2 fused with bias + log_softmax
    k_prop<<<pb, 256>>>(b, out, N, 1);
}